// round 15
// baseline (speedup 1.0000x reference)
#include <cuda_runtime.h>
#include <cuda_fp16.h>
#include <cstdint>

#define G_DIM 20000
#define P_DIM 4096
#define B_DIM 128
#define NCHUNK 625            // 20000 / 32
#define SPLITS 4
#define CPS 157               // chunks per K-split (last split: 154)

#define A_OFF    128          // A: 3 stages x 16384 (hi 8K, lo 8K)
#define RAW_OFF  49280        // raw W: 2 stages x 16384 (Wk 8K, Wa 8K)
#define CONV_OFF 82048        // conv: 2 stages x 8192
#define SMEM_TOTAL 98432

// ---------------- static scratch ----------------
__device__ __half g_in_hi[(size_t)B_DIM * G_DIM];
__device__ __half g_in_lo[(size_t)B_DIM * G_DIM];
__device__ float g_ph[(size_t)SPLITS * B_DIM * P_DIM];   // [s][b][p]
__device__ float g_pa[(size_t)SPLITS * B_DIM * P_DIM];

// ---------------- helpers ----------------
__device__ __forceinline__ uint32_t smem_u32(const void* p) {
    uint32_t a;
    asm("{ .reg .u64 t; cvta.to.shared.u64 t, %1; cvt.u32.u64 %0, t; }" : "=r"(a) : "l"(p));
    return a;
}
__device__ __forceinline__ void cp16(uint32_t d, const void* s) {
    asm volatile("cp.async.cg.shared.global [%0], [%1], 16;" :: "r"(d), "l"(s) : "memory");
}
__device__ __forceinline__ void ldsm4(uint32_t* r, uint32_t a) {
    asm volatile("ldmatrix.sync.aligned.m8n8.x4.shared.b16 {%0,%1,%2,%3}, [%4];"
                 : "=r"(r[0]), "=r"(r[1]), "=r"(r[2]), "=r"(r[3]) : "r"(a));
}
__device__ __forceinline__ void ldsm4t(uint32_t* r, uint32_t a) {
    asm volatile("ldmatrix.sync.aligned.m8n8.x4.trans.shared.b16 {%0,%1,%2,%3}, [%4];"
                 : "=r"(r[0]), "=r"(r[1]), "=r"(r[2]), "=r"(r[3]) : "r"(a));
}
__device__ __forceinline__ void mma16816(float* c, const uint32_t* a, const uint32_t* b) {
    asm volatile(
        "mma.sync.aligned.m16n8k16.row.col.f32.f16.f16.f32 "
        "{%0,%1,%2,%3}, {%4,%5,%6,%7}, {%8,%9}, {%0,%1,%2,%3};"
        : "+f"(c[0]), "+f"(c[1]), "+f"(c[2]), "+f"(c[3])
        : "r"(a[0]), "r"(a[1]), "r"(a[2]), "r"(a[3]), "r"(b[0]), "r"(b[1]));
}

// ---------------- prep: split inputs into fp16 hi/lo (exact 2-term) ----------------
__global__ void prep_k(const float* __restrict__ in) {
    int idx = blockIdx.x * 256 + threadIdx.x;
    if (idx >= B_DIM * G_DIM) return;
    float x = in[idx];
    __half h = __float2half_rn(x);
    g_in_hi[idx] = h;
    g_in_lo[idx] = __float2half_rn(x - __half2float(h));
}

// ---------------- main GEMM ----------------
__global__ void __launch_bounds__(256, 2) gemm_k(
    const float* __restrict__ Wk, const float* __restrict__ Mp, const float* __restrict__ Wa)
{
    extern __shared__ char smem[];
    const int tid = threadIdx.x;
    const int pt = blockIdx.x & 63;
    const int split = blockIdx.x >> 6;
    const int p0 = pt * 64;
    const int c0 = split * CPS;
    const int nch = min(CPS, NCHUNK - c0);
    const uint32_t sb = smem_u32(smem);

    auto issueA = [&](int stage, int gk) {
        #pragma unroll
        for (int j = 0; j < 4; j++) {
            int idx = tid + j * 256;
            int half_ = idx >> 9, b = (idx >> 2) & 127, kg = idx & 3;
            uint32_t dst = sb + A_OFF + stage * 16384 + half_ * 8192 + b * 64
                         + (uint32_t)((kg ^ ((b >> 1) & 3)) << 4);
            const __half* src = (half_ ? g_in_lo : g_in_hi) + (size_t)b * G_DIM + gk + kg * 8;
            cp16(dst, src);
        }
    };
    auto issueW = [&](int stage, int gk) {
        #pragma unroll
        for (int j = 0; j < 4; j++) {
            int idx = tid + j * 256;
            int arr = idx >> 9, r = (idx >> 4) & 31, c = idx & 15;
            uint32_t dst = sb + RAW_OFF + stage * 16384 + arr * 8192 + r * 256 + c * 16;
            const float* bp = arr ? Wa : Wk;
            cp16(dst, bp + (size_t)(gk + r) * P_DIM + p0 + c * 4);
        }
    };

    // convert-phase mapping: thread covers 4 (k,np) positions
    const int cnp = tid & 31;
    auto convert = [&](int stage, const float2* mp) {
        const float* raw = (const float*)(smem + RAW_OFF + stage * 16384);
        char* conv = smem + CONV_OFF + stage * 8192;
        #pragma unroll
        for (int j = 0; j < 4; j++) {
            int k = (tid + j * 256) >> 5, np = cnp;
            float2 wk = *(const float2*)(raw + k * 64 + np * 2);
            float2 wa = *(const float2*)(raw + 2048 + k * 64 + np * 2);
            __half2 hm = __floats2half2_rn(wk.x * mp[j].x, wk.y * mp[j].y);
            __half2 ha = __floats2half2_rn(wa.x, wa.y);
            uint32_t base = (uint32_t)k * 256 + (np & 3) * 4;
            uint32_t om = base + (uint32_t)((((np >> 2)) ^ (k & 7)) << 4);
            uint32_t oa = base + (uint32_t)(((8 + (np >> 2)) ^ (k & 7)) << 4);
            *(uint32_t*)(conv + om) = *reinterpret_cast<uint32_t*>(&hm);
            *(uint32_t*)(conv + oa) = *reinterpret_cast<uint32_t*>(&ha);
        }
    };

    // warp tiling: 4 M-warps x 2 N-warps; warp tile 32(M) x (32 masked + 32 att)(N)
    const int lane = tid & 31, wid = tid >> 5;
    const int wm = wid & 3, wn = wid >> 2;
    const int am0 = wm * 32 + (lane & 7) + ((lane >> 3) & 1) * 8;
    const int aswz = (am0 >> 1) & 3;
    const int lhi = lane >> 4;
    const int bk0 = (lane & 7) + ((lane >> 3) & 1) * 8;
    const int bk7 = bk0 & 7;

    float accM[2][4][4], accA[2][4][4];
    #pragma unroll
    for (int i = 0; i < 2; i++)
        #pragma unroll
        for (int j = 0; j < 4; j++)
            #pragma unroll
            for (int q = 0; q < 4; q++) { accM[i][j][q] = 0.f; accA[i][j][q] = 0.f; }

    // stage rotation: chunk i lives in A stage (i % 3); sp/sc/sn track i-1/i/i+1
    int sp = 2, sc = 0, sn = 1;

    issueA(0, c0 * 32);
    issueW(0, c0 * 32);
    asm volatile("cp.async.commit_group;" ::: "memory");

    for (int i = 0; i <= nch; i++) {
        if (i < nch) asm volatile("cp.async.wait_group 0;" ::: "memory");
        __syncthreads();   // chunk i landed & visible; all warps finished MMA(i-2)+convert(i-1)

        if (i + 1 < nch) {
            int gk = (c0 + i + 1) * 32;
            issueA(sn, gk);
            issueW((i + 1) & 1, gk);
            asm volatile("cp.async.commit_group;" ::: "memory");
        }

        float2 mp[4];
        if (i < nch) {       // issue mask LDGs early; latency hides under MMA block
            int gk = (c0 + i) * 32;
            #pragma unroll
            for (int j = 0; j < 4; j++) {
                int k = (tid + j * 256) >> 5;
                mp[j] = __ldg((const float2*)(Mp + (size_t)(gk + k) * P_DIM + p0 + cnp * 2));
            }
        }

        if (i >= 1) {        // MMA for chunk i-1
            const uint32_t abase = sb + A_OFF + (uint32_t)sp * 16384;
            const uint32_t cbase = sb + CONV_OFF + (uint32_t)((i - 1) & 1) * 8192;
            #pragma unroll
            for (int ks = 0; ks < 2; ks++) {
                uint32_t Ah[2][4], Al[2][4];
                #pragma unroll
                for (int mt = 0; mt < 2; mt++) {
                    uint32_t ab = abase + (uint32_t)(am0 + mt * 16) * 64
                                + (uint32_t)((((ks * 2 + lhi) ^ aswz)) << 4);
                    ldsm4(Ah[mt], ab);
                    ldsm4(Al[mt], ab + 8192);
                }
                const uint32_t rbase = cbase + (uint32_t)(ks * 16 + bk0) * 256;
                #pragma unroll
                for (int ntp = 0; ntp < 2; ntp++) {       // masked half: 2 terms
                    uint32_t Bm[4];
                    ldsm4t(Bm, rbase + (uint32_t)(((wn * 4 + ntp * 2 + lhi) ^ bk7) << 4));
                    #pragma unroll
                    for (int mt = 0; mt < 2; mt++)
                        #pragma unroll
                        for (int h = 0; h < 2; h++) {
                            float* C = accM[mt][ntp * 2 + h];
                            mma16816(C, Ah[mt], Bm + h * 2);   // A_hi * W
                            mma16816(C, Al[mt], Bm + h * 2);   // A_lo * W
                        }
                }
                #pragma unroll
                for (int ntp = 0; ntp < 2; ntp++) {       // att half: 1 term
                    uint32_t Ba[4];
                    ldsm4t(Ba, rbase + (uint32_t)(((8 + wn * 4 + ntp * 2 + lhi) ^ bk7) << 4));
                    #pragma unroll
                    for (int mt = 0; mt < 2; mt++)
                        #pragma unroll
                        for (int h = 0; h < 2; h++)
                            mma16816(accA[mt][ntp * 2 + h], Ah[mt], Ba + h * 2);
                }
            }
        }

        if (i < nch) convert(i & 1, mp);

        sp = sc; sc = sn; sn = (sn == 2) ? 0 : sn + 1;
    }

    // store partials [s][b][p]
    float* dm = g_ph + (size_t)split * B_DIM * P_DIM;
    float* da = g_pa + (size_t)split * B_DIM * P_DIM;
    #pragma unroll
    for (int mt = 0; mt < 2; mt++) {
        #pragma unroll
        for (int nt = 0; nt < 4; nt++) {
            int b = wm * 32 + mt * 16 + (lane >> 2);
            int p = p0 + wn * 32 + nt * 8 + (lane & 3) * 2;
            *(float2*)(dm + (size_t)b * P_DIM + p) = make_float2(accM[mt][nt][0], accM[mt][nt][1]);
            *(float2*)(dm + (size_t)(b + 8) * P_DIM + p) = make_float2(accM[mt][nt][2], accM[mt][nt][3]);
            *(float2*)(da + (size_t)b * P_DIM + p) = make_float2(accA[mt][nt][0], accA[mt][nt][1]);
            *(float2*)(da + (size_t)(b + 8) * P_DIM + p) = make_float2(accA[mt][nt][2], accA[mt][nt][3]);
        }
    }
}

// ---------------- epilogue: split-reduce + BN + tanh*sigmoid (register-resident) ----------------
__global__ void __launch_bounds__(128) epi_k(
    const float* __restrict__ attb, const float* __restrict__ gamma,
    const float* __restrict__ beta, float* __restrict__ out)
{
    const int tid = threadIdx.x;
    const int pl = tid & 31, bg = tid >> 5;
    const int p = blockIdx.x * 32 + pl;
    const int b0 = bg * 32;
    float h[32], a[32];
    float s1 = 0.f, s2 = 0.f;
    #pragma unroll
    for (int j = 0; j < 32; j++) {
        int b = b0 + j;
        float hh = 0.f, aa = 0.f;
        #pragma unroll
        for (int s = 0; s < 4; s++) {
            hh += g_ph[((size_t)s * B_DIM + b) * P_DIM + p];
            aa += g_pa[((size_t)s * B_DIM + b) * P_DIM + p];
        }
        h[j] = hh; a[j] = aa;
        s1 += hh; s2 += hh * hh;
    }
    __shared__ float sm1[128], sm2[128];
    sm1[tid] = s1; sm2[tid] = s2;
    __syncthreads();
    if (bg == 0) {
        sm1[pl] = sm1[pl] + sm1[32 + pl] + sm1[64 + pl] + sm1[96 + pl];
        sm2[pl] = sm2[pl] + sm2[32 + pl] + sm2[64 + pl] + sm2[96 + pl];
    }
    __syncthreads();
    float mean = sm1[pl] * (1.0f / 128.0f);
    float var  = sm2[pl] * (1.0f / 128.0f) - mean * mean;
    float scale = rsqrtf(var + 1e-5f) * gamma[p];
    float bet = beta[p], ab = attb[p];
    #pragma unroll
    for (int j = 0; j < 32; j++) {
        int b = b0 + j;
        float t = tanhf((h[j] - mean) * scale + bet);
        float sg = 1.0f / (1.0f + expf(-(a[j] + ab)));
        out[(size_t)b * P_DIM + p] = t * sg;                                    // outcome
        out[(size_t)B_DIM * P_DIM + B_DIM + (size_t)b * P_DIM + p] = sg;        // attention
    }
}

// ---------------- decision head ----------------
__global__ void __launch_bounds__(512) dec_k(
    const float* __restrict__ dw, const float* __restrict__ db, float* __restrict__ out)
{
    const int b = blockIdx.x, tid = threadIdx.x;
    float s = 0.f;
    #pragma unroll
    for (int j = 0; j < 8; j++) {
        int p = tid + j * 512;
        s += out[(size_t)b * P_DIM + p] * dw[p];
    }
    #pragma unroll
    for (int o = 16; o; o >>= 1) s += __shfl_xor_sync(0xffffffffu, s, o);
    __shared__ float sm[16];
    if ((tid & 31) == 0) sm[tid >> 5] = s;
    __syncthreads();
    if (tid == 0) {
        float t = 0.f;
        #pragma unroll
        for (int w = 0; w < 16; w++) t += sm[w];
        out[(size_t)B_DIM * P_DIM + b] = t + db[0];
    }
}

extern "C" void kernel_launch(void* const* d_in, const int* in_sizes, int n_in,
                              void* d_out, int out_size) {
    (void)in_sizes; (void)n_in; (void)out_size;
    const float* inputs = (const float*)d_in[0];
    const float* mapp   = (const float*)d_in[1];
    const float* kern   = (const float*)d_in[2];
    const float* attk   = (const float*)d_in[4];
    const float* attb   = (const float*)d_in[5];
    const float* gamma  = (const float*)d_in[6];
    const float* beta   = (const float*)d_in[7];
    const float* dw     = (const float*)d_in[8];
    const float* db     = (const float*)d_in[9];
    float* out = (float*)d_out;

    cudaFuncSetAttribute(gemm_k, cudaFuncAttributeMaxDynamicSharedMemorySize, SMEM_TOTAL);
    prep_k<<<(B_DIM * G_DIM + 255) / 256, 256>>>(inputs);
    gemm_k<<<256, 256, SMEM_TOTAL>>>(kern, mapp, attk);
    epi_k<<<P_DIM / 32, 128>>>(attb, gamma, beta, out);
    dec_k<<<B_DIM, 512>>>(dw, db, out);
}

// round 16
// speedup vs baseline: 1.2270x; 1.2270x over previous
#include <cuda_runtime.h>
#include <cuda_fp16.h>
#include <cstdint>

#define G_DIM 20000
#define P_DIM 4096
#define B_DIM 128
#define NCHUNK 625            // 20000 / 32
#define SPLITS 4
#define CPS 157               // chunks per K-split (last split: 154)

#define A_OFF    128          // A: 2 stages x 8192 (fp16 hi only)
#define RAW_OFF  16512        // raw W: 2 stages x 24576 (Wk 8K, Mp 8K, Wa 8K)
#define CONV_OFF 65664        // conv fp16 W: 8192
#define SMEM_TOTAL 73856

// ---------------- static scratch ----------------
__device__ __half g_in_hi[(size_t)B_DIM * G_DIM];
__device__ float g_ph[(size_t)SPLITS * B_DIM * P_DIM];   // [s][b][p]
__device__ float g_pa[(size_t)SPLITS * B_DIM * P_DIM];

// ---------------- helpers ----------------
__device__ __forceinline__ uint32_t smem_u32(const void* p) {
    uint32_t a;
    asm("{ .reg .u64 t; cvta.to.shared.u64 t, %1; cvt.u32.u64 %0, t; }" : "=r"(a) : "l"(p));
    return a;
}
__device__ __forceinline__ void cp16(uint32_t d, const void* s) {
    asm volatile("cp.async.cg.shared.global [%0], [%1], 16;" :: "r"(d), "l"(s) : "memory");
}
__device__ __forceinline__ void ldsm4(uint32_t* r, uint32_t a) {
    asm volatile("ldmatrix.sync.aligned.m8n8.x4.shared.b16 {%0,%1,%2,%3}, [%4];"
                 : "=r"(r[0]), "=r"(r[1]), "=r"(r[2]), "=r"(r[3]) : "r"(a));
}
__device__ __forceinline__ void ldsm4t(uint32_t* r, uint32_t a) {
    asm volatile("ldmatrix.sync.aligned.m8n8.x4.trans.shared.b16 {%0,%1,%2,%3}, [%4];"
                 : "=r"(r[0]), "=r"(r[1]), "=r"(r[2]), "=r"(r[3]) : "r"(a));
}
__device__ __forceinline__ void mma16816(float* c, const uint32_t* a, const uint32_t* b) {
    asm volatile(
        "mma.sync.aligned.m16n8k16.row.col.f32.f16.f16.f32 "
        "{%0,%1,%2,%3}, {%4,%5,%6,%7}, {%8,%9}, {%0,%1,%2,%3};"
        : "+f"(c[0]), "+f"(c[1]), "+f"(c[2]), "+f"(c[3])
        : "r"(a[0]), "r"(a[1]), "r"(a[2]), "r"(a[3]), "r"(b[0]), "r"(b[1]));
}

// ---------------- prep: inputs -> fp16 ----------------
__global__ void prep_k(const float* __restrict__ in) {
    int idx = blockIdx.x * 256 + threadIdx.x;
    if (idx >= B_DIM * G_DIM) return;
    g_in_hi[idx] = __float2half_rn(in[idx]);
}

// ---------------- main GEMM ----------------
// smem: [128, 16512)   A: 2 stages x 8192   [b][32k] swizzled fp16
//       [16512,65664)  raw W: 2 stages x (Wk 8K, Mp 8K, Wa 8K)
//       [65664,73856)  fp16 W: [32k][masked 64 | att 64] swizzled (8K)
__global__ void __launch_bounds__(256, 2) gemm_k(
    const float* __restrict__ Wk, const float* __restrict__ Mp, const float* __restrict__ Wa)
{
    extern __shared__ char smem[];
    const int tid = threadIdx.x;
    const int pt = blockIdx.x & 63;
    const int split = blockIdx.x >> 6;
    const int p0 = pt * 64;
    const int c0 = split * CPS;
    const int nch = min(CPS, NCHUNK - c0);
    const uint32_t sb = smem_u32(smem);

    auto issueA = [&](int stage, int gk) {
        #pragma unroll
        for (int j = 0; j < 2; j++) {
            int idx = tid + j * 256;
            int b = idx >> 2, kg = idx & 3;
            uint32_t dst = sb + A_OFF + stage * 8192 + b * 64
                         + (uint32_t)((kg ^ ((b >> 1) & 3)) << 4);
            cp16(dst, g_in_hi + (size_t)b * G_DIM + gk + kg * 8);
        }
    };
    auto issueW = [&](int stage, int gk) {
        #pragma unroll
        for (int j = 0; j < 6; j++) {
            int idx = tid + j * 256;
            int arr = idx >> 9, r = (idx >> 4) & 31, c = idx & 15;
            uint32_t dst = sb + RAW_OFF + stage * 24576 + arr * 8192 + r * 256 + c * 16;
            const float* bp = (arr == 0) ? Wk : (arr == 1 ? Mp : Wa);
            cp16(dst, bp + (size_t)(gk + r) * P_DIM + p0 + c * 4);
        }
    };
    auto convert = [&](int stage) {
        const float* raw = (const float*)(smem + RAW_OFF + stage * 24576);
        #pragma unroll
        for (int j = 0; j < 4; j++) {
            int pi = tid + j * 256;
            int k = pi >> 5, np = pi & 31;
            float2 wk = *(const float2*)(raw + k * 64 + np * 2);
            float2 mp = *(const float2*)(raw + 2048 + k * 64 + np * 2);
            float2 wa = *(const float2*)(raw + 4096 + k * 64 + np * 2);
            __half2 hm = __floats2half2_rn(wk.x * mp.x, wk.y * mp.y);
            __half2 ha = __floats2half2_rn(wa.x, wa.y);
            uint32_t base = (uint32_t)k * 256 + (np & 3) * 4;
            uint32_t om = base + (uint32_t)((((np >> 2)) ^ (k & 7)) << 4);
            uint32_t oa = base + (uint32_t)(((8 + (np >> 2)) ^ (k & 7)) << 4);
            *(uint32_t*)(smem + CONV_OFF + om) = *reinterpret_cast<uint32_t*>(&hm);
            *(uint32_t*)(smem + CONV_OFF + oa) = *reinterpret_cast<uint32_t*>(&ha);
        }
    };

    // warp tiling: 4 M-warps x 2 N-warps; warp tile 32(M) x (32 masked + 32 att)(N)
    const int lane = tid & 31, wid = tid >> 5;
    const int wm = wid & 3, wn = wid >> 2;
    const int am0 = wm * 32 + (lane & 7) + ((lane >> 3) & 1) * 8;
    const int aswz = (am0 >> 1) & 3;
    const int lhi = lane >> 4;
    const int bk0 = (lane & 7) + ((lane >> 3) & 1) * 8;
    const int bk7 = bk0 & 7;

    float accM[2][4][4], accA[2][4][4];
    #pragma unroll
    for (int i = 0; i < 2; i++)
        #pragma unroll
        for (int j = 0; j < 4; j++)
            #pragma unroll
            for (int q = 0; q < 4; q++) { accM[i][j][q] = 0.f; accA[i][j][q] = 0.f; }

    issueA(0, c0 * 32);
    issueW(0, c0 * 32);
    asm volatile("cp.async.commit_group;" ::: "memory");

    for (int i = 0; i < nch; i++) {
        const int st = i & 1;
        asm volatile("cp.async.wait_group 0;" ::: "memory");
        __syncthreads();                       // all warps past mma(i-1); stage data visible
        if (i + 1 < nch) { issueA(st ^ 1, (c0 + i + 1) * 32); issueW(st ^ 1, (c0 + i + 1) * 32); }
        asm volatile("cp.async.commit_group;" ::: "memory");
        convert(st);
        __syncthreads();
        #pragma unroll
        for (int ks = 0; ks < 2; ks++) {
            uint32_t Ah[2][4];
            #pragma unroll
            for (int mt = 0; mt < 2; mt++) {
                uint32_t ab = sb + A_OFF + st * 8192 + (uint32_t)(am0 + mt * 16) * 64
                            + (uint32_t)((((ks * 2 + lhi) ^ aswz)) << 4);
                ldsm4(Ah[mt], ab);
            }
            const uint32_t rbase = sb + CONV_OFF + (uint32_t)(ks * 16 + bk0) * 256;
            #pragma unroll
            for (int ntp = 0; ntp < 2; ntp++) {       // masked half
                uint32_t Bm[4];
                ldsm4t(Bm, rbase + (uint32_t)(((wn * 4 + ntp * 2 + lhi) ^ bk7) << 4));
                #pragma unroll
                for (int mt = 0; mt < 2; mt++)
                    #pragma unroll
                    for (int h = 0; h < 2; h++)
                        mma16816(accM[mt][ntp * 2 + h], Ah[mt], Bm + h * 2);
            }
            #pragma unroll
            for (int ntp = 0; ntp < 2; ntp++) {       // att half
                uint32_t Ba[4];
                ldsm4t(Ba, rbase + (uint32_t)(((8 + wn * 4 + ntp * 2 + lhi) ^ bk7) << 4));
                #pragma unroll
                for (int mt = 0; mt < 2; mt++)
                    #pragma unroll
                    for (int h = 0; h < 2; h++)
                        mma16816(accA[mt][ntp * 2 + h], Ah[mt], Ba + h * 2);
            }
        }
    }

    // store partials [s][b][p]
    float* dm = g_ph + (size_t)split * B_DIM * P_DIM;
    float* da = g_pa + (size_t)split * B_DIM * P_DIM;
    #pragma unroll
    for (int mt = 0; mt < 2; mt++) {
        #pragma unroll
        for (int nt = 0; nt < 4; nt++) {
            int b = wm * 32 + mt * 16 + (lane >> 2);
            int p = p0 + wn * 32 + nt * 8 + (lane & 3) * 2;
            *(float2*)(dm + (size_t)b * P_DIM + p) = make_float2(accM[mt][nt][0], accM[mt][nt][1]);
            *(float2*)(dm + (size_t)(b + 8) * P_DIM + p) = make_float2(accM[mt][nt][2], accM[mt][nt][3]);
            *(float2*)(da + (size_t)b * P_DIM + p) = make_float2(accA[mt][nt][0], accA[mt][nt][1]);
            *(float2*)(da + (size_t)(b + 8) * P_DIM + p) = make_float2(accA[mt][nt][2], accA[mt][nt][3]);
        }
    }
}

// ---------------- epilogue: split-reduce + BN + tanh*sigmoid (register-resident) ----------------
__global__ void __launch_bounds__(128) epi_k(
    const float* __restrict__ attb, const float* __restrict__ gamma,
    const float* __restrict__ beta, float* __restrict__ out)
{
    const int tid = threadIdx.x;
    const int pl = tid & 31, bg = tid >> 5;
    const int p = blockIdx.x * 32 + pl;
    const int b0 = bg * 32;
    float h[32], a[32];
    float s1 = 0.f, s2 = 0.f;
    #pragma unroll
    for (int j = 0; j < 32; j++) {
        int b = b0 + j;
        float hh = 0.f, aa = 0.f;
        #pragma unroll
        for (int s = 0; s < 4; s++) {
            hh += g_ph[((size_t)s * B_DIM + b) * P_DIM + p];
            aa += g_pa[((size_t)s * B_DIM + b) * P_DIM + p];
        }
        h[j] = hh; a[j] = aa;
        s1 += hh; s2 += hh * hh;
    }
    __shared__ float sm1[128], sm2[128];
    sm1[tid] = s1; sm2[tid] = s2;
    __syncthreads();
    if (bg == 0) {
        sm1[pl] = sm1[pl] + sm1[32 + pl] + sm1[64 + pl] + sm1[96 + pl];
        sm2[pl] = sm2[pl] + sm2[32 + pl] + sm2[64 + pl] + sm2[96 + pl];
    }
    __syncthreads();
    float mean = sm1[pl] * (1.0f / 128.0f);
    float var  = sm2[pl] * (1.0f / 128.0f) - mean * mean;
    float scale = rsqrtf(var + 1e-5f) * gamma[p];
    float bet = beta[p], ab = attb[p];
    #pragma unroll
    for (int j = 0; j < 32; j++) {
        int b = b0 + j;
        float t = tanhf((h[j] - mean) * scale + bet);
        float sg = 1.0f / (1.0f + expf(-(a[j] + ab)));
        out[(size_t)b * P_DIM + p] = t * sg;                                    // outcome
        out[(size_t)B_DIM * P_DIM + B_DIM + (size_t)b * P_DIM + p] = sg;        // attention
    }
}

// ---------------- decision head ----------------
__global__ void __launch_bounds__(512) dec_k(
    const float* __restrict__ dw, const float* __restrict__ db, float* __restrict__ out)
{
    const int b = blockIdx.x, tid = threadIdx.x;
    float s = 0.f;
    #pragma unroll
    for (int j = 0; j < 8; j++) {
        int p = tid + j * 512;
        s += out[(size_t)b * P_DIM + p] * dw[p];
    }
    #pragma unroll
    for (int o = 16; o; o >>= 1) s += __shfl_xor_sync(0xffffffffu, s, o);
    __shared__ float sm[16];
    if ((tid & 31) == 0) sm[tid >> 5] = s;
    __syncthreads();
    if (tid == 0) {
        float t = 0.f;
        #pragma unroll
        for (int w = 0; w < 16; w++) t += sm[w];
        out[(size_t)B_DIM * P_DIM + b] = t + db[0];
    }
}

extern "C" void kernel_launch(void* const* d_in, const int* in_sizes, int n_in,
                              void* d_out, int out_size) {
    (void)in_sizes; (void)n_in; (void)out_size;
    const float* inputs = (const float*)d_in[0];
    const float* mapp   = (const float*)d_in[1];
    const float* kern   = (const float*)d_in[2];
    const float* attk   = (const float*)d_in[4];
    const float* attb   = (const float*)d_in[5];
    const float* gamma  = (const float*)d_in[6];
    const float* beta   = (const float*)d_in[7];
    const float* dw     = (const float*)d_in[8];
    const float* db     = (const float*)d_in[9];
    float* out = (float*)d_out;

    cudaFuncSetAttribute(gemm_k, cudaFuncAttributeMaxDynamicSharedMemorySize, SMEM_TOTAL);
    prep_k<<<(B_DIM * G_DIM + 255) / 256, 256>>>(inputs);
    gemm_k<<<256, 256, SMEM_TOTAL>>>(kern, mapp, attk);
    epi_k<<<P_DIM / 32, 128>>>(attb, gamma, beta, out);
    dec_k<<<B_DIM, 512>>>(dw, db, out);
}